// round 11
// baseline (speedup 1.0000x reference)
#include <cuda_runtime.h>
#include <math.h>
#include <stdint.h>

// Problem constants
#define EDIM 384
#define GDIM 256
#define HNUM 6
#define DHH  64
#define OUTD 256
#define HE   (HNUM*EDIM)   // 2304
#define CHUNK 16
#define NBUF 4
#define UNIT 128
#define SLOTS 8            // MAX_N 1024 / UNIT
#define CFLOATS (CHUNK*EDIM)                    // 6144 floats per buffer
#define SMEM_X (NBUF*CFLOATS*4 + HNUM*EDIM*4)   // 98304 + 9216 = 107520 B
#define BLK 512

// ---------------- device scratch ----------------
__device__ __align__(16) float g_wk[HNUM*EDIM];
__device__ __align__(16) float g_Wc[OUTD*EDIM];      // Wp @ Wo
__device__ __align__(16) float g_cb[OUTD];           // Wp.bo + bp
__device__            int   g_off[GDIM + 1];
__device__ __align__(16) float g_accx[GDIM*HE];      // merged attn-weighted x sums
__device__ __align__(16) float g_pooled[GDIM*EDIM];  // pooled incl. bv
// per-unit softmax partials; pacc layout [u][e][8] (heads padded to 8)
__device__ __align__(16) float g_pacc[(size_t)GDIM*SLOTS*EDIM*8];
__device__ __align__(16) float g_pm[GDIM*SLOTS*HNUM];
__device__ __align__(16) float g_psum[GDIM*SLOTS*HNUM];

// ---------------- helpers ----------------
__device__ __forceinline__ float warp_sum(float v) {
#pragma unroll
    for (int s = 16; s > 0; s >>= 1) v += __shfl_xor_sync(0xffffffffu, v, s);
    return v;
}
__device__ __forceinline__ void cp_async16(uint32_t saddr, const void* gaddr) {
    asm volatile("cp.async.cg.shared.global [%0], [%1], 16;" :: "r"(saddr), "l"(gaddr));
}
__device__ __forceinline__ void cp_commit() {
    asm volatile("cp.async.commit_group;");
}
__device__ __forceinline__ void cp_wait_n(int k) {
    if (k <= 0)      asm volatile("cp.async.wait_group 0;");
    else if (k == 1) asm volatile("cp.async.wait_group 1;");
    else             asm volatile("cp.async.wait_group 2;");
}

// ---------------- prep: wkq (blocks 0..5) + scan (6) + cb (7..28) ----------
__global__ void __launch_bounds__(EDIM)
prep_kernel(const float* __restrict__ Wq, const float* __restrict__ query,
            const float* __restrict__ bq, const float* __restrict__ Wk,
            const int* __restrict__ sizes, const float* __restrict__ Wp,
            const float* __restrict__ bo, const float* __restrict__ bp) {
    int b = blockIdx.x;
    int tid = threadIdx.x;
    int warp = tid >> 5;
    int lane = tid & 31;
    if (b < HNUM) {
        int h = b;
        __shared__ float qs[DHH];
        for (int d = warp; d < DHH; d += 12) {
            int row = h * DHH + d;
            float s = 0.f;
            for (int j = lane; j < EDIM; j += 32) s += Wq[(size_t)row * EDIM + j] * query[j];
            s = warp_sum(s);
            if (lane == 0) qs[d] = (s + bq[row]) * 0.125f;
        }
        __syncthreads();
        float s = 0.f;
#pragma unroll 8
        for (int d = 0; d < DHH; d++)
            s += qs[d] * Wk[(size_t)(h * DHH + d) * EDIM + tid];
        g_wk[h * EDIM + tid] = s;
    } else if (b == HNUM) {
        __shared__ int s[GDIM];
        if (tid < GDIM) s[tid] = sizes[tid];
        __syncthreads();
        for (int d = 1; d < GDIM; d <<= 1) {
            int add = (tid < GDIM && tid >= d) ? s[tid - d] : 0;
            __syncthreads();
            if (tid < GDIM) s[tid] += add;
            __syncthreads();
        }
        if (tid < GDIM) {
            g_off[tid] = s[tid] - sizes[tid];
            if (tid == GDIM - 1) g_off[GDIM] = s[tid];
        }
    } else {
        int gw = (b - HNUM - 1) * 12 + warp;
        if (gw < OUTD) {
            float s = 0.f;
            for (int j = lane; j < EDIM; j += 32) s += Wp[(size_t)gw * EDIM + j] * bo[j];
            s = warp_sum(s);
            if (lane == 0) g_cb[gw] = s + bp[gw];
        }
    }
}

// ---------------- 64x32-tiled fp32 GEMM, 4x4 microtile, 128 threads ------
template <bool TB, bool BIAS>
__global__ void __launch_bounds__(128)
gemm_s(const float* __restrict__ A, int lda,
       const float* __restrict__ B, int ldb,
       float* __restrict__ C, int ldc,
       const float* __restrict__ bias,
       int M, int N, int K,
       int zA, int zB, int zC, int zBias) {
    A += (size_t)blockIdx.z * zA;
    B += (size_t)blockIdx.z * zB;
    C += (size_t)blockIdx.z * zC;
    if (BIAS) bias += (size_t)blockIdx.z * zBias;

    __shared__ float As[32][68];
    __shared__ float Bs[32][36];
    int tid = threadIdx.x;
    int bm = blockIdx.y * 64, bn = blockIdx.x * 32;
    int tx = tid & 7, ty = tid >> 3;

    float acc[4][4];
#pragma unroll
    for (int i = 0; i < 4; i++)
#pragma unroll
        for (int j = 0; j < 4; j++) acc[i][j] = 0.f;

    for (int k0 = 0; k0 < K; k0 += 32) {
        {
            int kk = tid & 31, mb = tid >> 5;
#pragma unroll
            for (int i = 0; i < 16; i++) {
                int mm = mb + i * 4;
                As[kk][mm] = A[(size_t)(bm + mm) * lda + k0 + kk];
            }
        }
        if (TB) {
            int kk = tid & 31, nb = tid >> 5;
#pragma unroll
            for (int i = 0; i < 8; i++) {
                int nn = nb + i * 4;
                Bs[kk][nn] = B[(size_t)(bn + nn) * ldb + k0 + kk];
            }
        } else {
            int nn = tid & 31, kb = tid >> 5;
#pragma unroll
            for (int i = 0; i < 8; i++) {
                int k2 = kb + i * 4;
                Bs[k2][nn] = B[(size_t)(k0 + k2) * ldb + bn + nn];
            }
        }
        __syncthreads();
#pragma unroll
        for (int kk = 0; kk < 32; kk++) {
            float4 a = *(const float4*)&As[kk][ty * 4];
            float4 bb = *(const float4*)&Bs[kk][tx * 4];
            acc[0][0] = fmaf(a.x, bb.x, acc[0][0]); acc[0][1] = fmaf(a.x, bb.y, acc[0][1]);
            acc[0][2] = fmaf(a.x, bb.z, acc[0][2]); acc[0][3] = fmaf(a.x, bb.w, acc[0][3]);
            acc[1][0] = fmaf(a.y, bb.x, acc[1][0]); acc[1][1] = fmaf(a.y, bb.y, acc[1][1]);
            acc[1][2] = fmaf(a.y, bb.z, acc[1][2]); acc[1][3] = fmaf(a.y, bb.w, acc[1][3]);
            acc[2][0] = fmaf(a.z, bb.x, acc[2][0]); acc[2][1] = fmaf(a.z, bb.y, acc[2][1]);
            acc[2][2] = fmaf(a.z, bb.z, acc[2][2]); acc[2][3] = fmaf(a.z, bb.w, acc[2][3]);
            acc[3][0] = fmaf(a.w, bb.x, acc[3][0]); acc[3][1] = fmaf(a.w, bb.y, acc[3][1]);
            acc[3][2] = fmaf(a.w, bb.z, acc[3][2]); acc[3][3] = fmaf(a.w, bb.w, acc[3][3]);
        }
        __syncthreads();
    }
    float4 bv4 = make_float4(0.f, 0.f, 0.f, 0.f);
    if (BIAS) bv4 = *(const float4*)&bias[bn + tx * 4];
#pragma unroll
    for (int i = 0; i < 4; i++) {
        int gm = bm + ty * 4 + i;
        float4 o = make_float4(acc[i][0] + bv4.x, acc[i][1] + bv4.y,
                               acc[i][2] + bv4.z, acc[i][3] + bv4.w);
        *(float4*)&C[(size_t)gm * ldc + bn + tx * 4] = o;
    }
}

// ---------------- attention unit kernel: warp-specialized pipeline ---------
// 512 threads: warps 0-3 = producers (load + scores + softmax for chunk c+1),
// warps 4-15 = consumers (384 columns, accumulate chunk c). 4-deep cp.async ring.
extern __shared__ float dyn_s[];   // [NBUF][CFLOATS] x-buffers, then w_s[2304]

__global__ void __launch_bounds__(BLK, 2)
attn_unit_kernel(const float* __restrict__ x, const int* __restrict__ sizes) {
    __shared__ float s_sc[2][CHUNK][8];      // exp'd scores, double-buffered
    __shared__ float s_scale[2][HNUM];
    __shared__ float s_run_m[HNUM], s_run_sum[HNUM];

    int u = blockIdx.x;
    int g = u >> 3;
    int slot = u & (SLOTS - 1);
    int size = sizes[g];
    int ustart = slot * UNIT;
    if (ustart >= size) return;
    int ucnt = min(UNIT, size - ustart);
    int off = g_off[g] + ustart;
    int nchunks = (ucnt + CHUNK - 1) / CHUNK;

    int tid = threadIdx.x;
    int warp = tid >> 5;
    int lane = tid & 31;
    bool producer = (warp < 4);

    float* xbuf = dyn_s;
    float* w_s = dyn_s + NBUF * CFLOATS;
    const float4* ws4 = (const float4*)w_s;

    // stage score weights into smem (all threads)
    for (int i = tid; i < HNUM * EDIM; i += BLK) w_s[i] = g_wk[i];
    if (tid < HNUM) { s_run_m[tid] = -1e30f; s_run_sum[tid] = 0.f; }

    uint32_t sb = (uint32_t)__cvta_generic_to_shared(xbuf);

    // prologue: issue chunks 0,1 (producers only)
    if (producer) {
#pragma unroll
        for (int j = 0; j < 2; j++) {
            if (j < nchunks) {
                int cntj = min(CHUNK, ucnt - j * CHUNK);
                const float4* gx = (const float4*)(x + (size_t)(off + j * CHUNK) * EDIM);
                uint32_t dst = sb + (uint32_t)((j & 3) * CFLOATS * 4);
                int nf4 = cntj * (EDIM / 4);
                for (int i = tid; i < nf4; i += 128)
                    cp_async16(dst + i * 16, gx + i);
                cp_commit();
            }
        }
    }

    float acc[HNUM];
#pragma unroll
    for (int h = 0; h < HNUM; h++) acc[h] = 0.f;
    int e = tid - 128;   // consumer column (valid when !producer)

    for (int c = -1; c < nchunks; c++) {
        __syncthreads();   // prev iter's consumer done -> safe to overwrite ring buf

        if (producer) {
            int hi = c + 3;
            if (hi < nchunks) {
                int cntj = min(CHUNK, ucnt - hi * CHUNK);
                const float4* gx = (const float4*)(x + (size_t)(off + hi * CHUNK) * EDIM);
                uint32_t dst = sb + (uint32_t)((hi & 3) * CFLOATS * 4);
                int nf4 = cntj * (EDIM / 4);
                for (int i = tid; i < nf4; i += 128)
                    cp_async16(dst + i * 16, gx + i);
                cp_commit();
            }
            int k = nchunks - c - 2;           // #issued chunks beyond c+1
            cp_wait_n(k);                      // ensures chunk c+1 resident

            if (c + 1 < nchunks) {
                int cc = c + 1, b = cc & 1;
                int cnt = min(CHUNK, ucnt - cc * CHUNK);
                const float* buf = xbuf + (cc & 3) * CFLOATS;

                // scores, two nodes per warp-pass for SHFL ILP
                for (int nn = warp * 2; nn < cnt; nn += 8) {
                    int nn1 = min(nn + 1, cnt - 1);
                    const float4* r0 = (const float4*)(buf + nn * EDIM);
                    const float4* r1 = (const float4*)(buf + nn1 * EDIM);
                    float4 a0 = r0[lane], a1 = r0[lane + 32], a2 = r0[lane + 64];
                    float4 b0 = r1[lane], b1 = r1[lane + 32], b2 = r1[lane + 64];
                    float p0[HNUM], p1[HNUM];
#pragma unroll
                    for (int h = 0; h < HNUM; h++) {
                        const float4* wp = ws4 + h * 96 + lane;
                        float4 w0 = wp[0], w1 = wp[32], w2 = wp[64];
                        float s0, s1;
                        s0 = w0.x * a0.x;              s1 = w0.x * b0.x;
                        s0 = fmaf(w0.y, a0.y, s0);     s1 = fmaf(w0.y, b0.y, s1);
                        s0 = fmaf(w0.z, a0.z, s0);     s1 = fmaf(w0.z, b0.z, s1);
                        s0 = fmaf(w0.w, a0.w, s0);     s1 = fmaf(w0.w, b0.w, s1);
                        s0 = fmaf(w1.x, a1.x, s0);     s1 = fmaf(w1.x, b1.x, s1);
                        s0 = fmaf(w1.y, a1.y, s0);     s1 = fmaf(w1.y, b1.y, s1);
                        s0 = fmaf(w1.z, a1.z, s0);     s1 = fmaf(w1.z, b1.z, s1);
                        s0 = fmaf(w1.w, a1.w, s0);     s1 = fmaf(w1.w, b1.w, s1);
                        s0 = fmaf(w2.x, a2.x, s0);     s1 = fmaf(w2.x, b2.x, s1);
                        s0 = fmaf(w2.y, a2.y, s0);     s1 = fmaf(w2.y, b2.y, s1);
                        s0 = fmaf(w2.z, a2.z, s0);     s1 = fmaf(w2.z, b2.z, s1);
                        s0 = fmaf(w2.w, a2.w, s0);     s1 = fmaf(w2.w, b2.w, s1);
                        p0[h] = s0; p1[h] = s1;
                    }
#pragma unroll
                    for (int sft = 16; sft > 0; sft >>= 1) {
#pragma unroll
                        for (int h = 0; h < HNUM; h++) {
                            p0[h] += __shfl_xor_sync(0xffffffffu, p0[h], sft);
                            p1[h] += __shfl_xor_sync(0xffffffffu, p1[h], sft);
                        }
                    }
                    if (lane == 0) {
#pragma unroll
                        for (int h = 0; h < HNUM; h++) {
                            s_sc[b][nn][h] = p0[h];
                            if (nn + 1 < cnt) s_sc[b][nn + 1][h] = p1[h];
                        }
                    }
                }
                asm volatile("bar.sync 1, 128;" ::: "memory");   // producer warps only

                // online softmax: warp w handles heads w, w+4
                for (int h = warp; h < HNUM; h += 4) {
                    float v = (lane < cnt) ? s_sc[b][lane][h] : -1e30f;
#pragma unroll
                    for (int sft = 8; sft > 0; sft >>= 1)
                        v = fmaxf(v, __shfl_xor_sync(0xffffffffu, v, sft));
                    float newm = fmaxf(s_run_m[h], v);
                    float ev = (lane < cnt) ? __expf(s_sc[b][lane][h] - newm) : 0.f;
                    if (lane < cnt) s_sc[b][lane][h] = ev;
                    float sum = ev;
#pragma unroll
                    for (int sft = 8; sft > 0; sft >>= 1)
                        sum += __shfl_xor_sync(0xffffffffu, sum, sft);
                    if (lane == 0) {
                        float sc = __expf(s_run_m[h] - newm);
                        s_scale[b][h] = sc;
                        s_run_sum[h] = s_run_sum[h] * sc + sum;
                        s_run_m[h] = newm;
                    }
                }
            }
        } else if (c >= 0) {
            // consumers: accumulate chunk c
            int b = c & 1;
            int cnt = min(CHUNK, ucnt - c * CHUNK);
            const float* buf = xbuf + (c & 3) * CFLOATS + e;
#pragma unroll
            for (int h = 0; h < HNUM; h++) acc[h] *= s_scale[b][h];
            for (int nn = 0; nn < cnt; nn++) {
                float xv = buf[nn * EDIM];
                float4 a4 = *(const float4*)&s_sc[b][nn][0];
                float2 a2 = *(const float2*)&s_sc[b][nn][4];
                acc[0] = fmaf(a4.x, xv, acc[0]);
                acc[1] = fmaf(a4.y, xv, acc[1]);
                acc[2] = fmaf(a4.z, xv, acc[2]);
                acc[3] = fmaf(a4.w, xv, acc[3]);
                acc[4] = fmaf(a2.x, xv, acc[4]);
                acc[5] = fmaf(a2.y, xv, acc[5]);
            }
        }
    }

    // write unnormalized partials: pacc[u][e][8]
    if (!producer) {
        float4* pp = (float4*)&g_pacc[((size_t)u * EDIM + e) * 8];
        pp[0] = make_float4(acc[0], acc[1], acc[2], acc[3]);
        pp[1] = make_float4(acc[4], acc[5], 0.f, 0.f);
    }
    if (tid < HNUM) {
        g_pm[u * HNUM + tid] = s_run_m[tid];
        g_psum[u * HNUM + tid] = s_run_sum[tid];
    }
}

// ---------------- merge partials -> normalized accx ----------------
__global__ void __launch_bounds__(EDIM)
merge_kernel(const int* __restrict__ sizes) {
    __shared__ float s_w[SLOTS][HNUM];
    int g = blockIdx.x;
    int size = sizes[g];
    int nslots = (size + UNIT - 1) / UNIT;
    int tid = threadIdx.x;

    if (tid < HNUM) {
        int h = tid;
        float M = -1e30f;
        for (int s = 0; s < nslots; s++)
            M = fmaxf(M, g_pm[(g * SLOTS + s) * HNUM + h]);
        float denom = 0.f;
        for (int s = 0; s < nslots; s++) {
            float sc = __expf(g_pm[(g * SLOTS + s) * HNUM + h] - M);
            s_w[s][h] = sc;
            denom += sc * g_psum[(g * SLOTS + s) * HNUM + h];
        }
        float inv = 1.f / denom;
        for (int s = 0; s < nslots; s++) s_w[s][h] *= inv;
    }
    __syncthreads();

    float acc[HNUM];
#pragma unroll
    for (int h = 0; h < HNUM; h++) acc[h] = 0.f;
    for (int s = 0; s < nslots; s++) {
        const float4* pp = (const float4*)&g_pacc[((size_t)(g * SLOTS + s) * EDIM + tid) * 8];
        float4 p0 = pp[0];
        float4 p1 = pp[1];
        acc[0] = fmaf(s_w[s][0], p0.x, acc[0]);
        acc[1] = fmaf(s_w[s][1], p0.y, acc[1]);
        acc[2] = fmaf(s_w[s][2], p0.z, acc[2]);
        acc[3] = fmaf(s_w[s][3], p0.w, acc[3]);
        acc[4] = fmaf(s_w[s][4], p1.x, acc[4]);
        acc[5] = fmaf(s_w[s][5], p1.y, acc[5]);
    }
#pragma unroll
    for (int h = 0; h < HNUM; h++)
        g_accx[(size_t)g * HE + h * EDIM + tid] = acc[h];
}

// ---------------- launch ----------------
extern "C" void kernel_launch(void* const* d_in, const int* in_sizes, int n_in,
                              void* d_out, int out_size) {
    const float* node_feat = (const float*)d_in[0];
    const int*   sizes     = (const int*)d_in[1];
    const float* query     = (const float*)d_in[2];
    const float* Wq        = (const float*)d_in[3];
    const float* bq        = (const float*)d_in[4];
    const float* Wk        = (const float*)d_in[5];
    /* bk = d_in[6] cancels in softmax */
    const float* Wv        = (const float*)d_in[7];
    const float* bv        = (const float*)d_in[8];
    const float* Wo        = (const float*)d_in[9];
    const float* bo        = (const float*)d_in[10];
    const float* Wp        = (const float*)d_in[11];
    const float* bp        = (const float*)d_in[12];
    float* out = (float*)d_out;

    float *pWc, *pcb, *paccx, *ppooled;
    cudaGetSymbolAddress((void**)&pWc, g_Wc);
    cudaGetSymbolAddress((void**)&pcb, g_cb);
    cudaGetSymbolAddress((void**)&paccx, g_accx);
    cudaGetSymbolAddress((void**)&ppooled, g_pooled);

    cudaFuncSetAttribute(attn_unit_kernel,
                         cudaFuncAttributeMaxDynamicSharedMemorySize, SMEM_X);

    // prep: wkq + scan + cb in one launch
    prep_kernel<<<HNUM + 1 + 22, EDIM>>>(Wq, query, bq, Wk, sizes, Wp, bo, bp);

    // Wc = Wp @ Wo   [256,384]
    gemm_s<false, false><<<dim3(EDIM / 32, OUTD / 64, 1), 128>>>(
        Wp, EDIM, Wo, EDIM, pWc, EDIM, nullptr, OUTD, EDIM, EDIM, 0, 0, 0, 0);

    // attention partials + merge
    attn_unit_kernel<<<GDIM * SLOTS, BLK, SMEM_X>>>(node_feat, sizes);
    merge_kernel<<<GDIM, EDIM>>>(sizes);

    // pooled[g, h*64+d] = bv + Wv_h . accx_h   (batched over h)
    gemm_s<true, true><<<dim3(DHH / 32, GDIM / 64, HNUM), 128>>>(
        paccx, HE, Wv, EDIM, ppooled, EDIM, bv,
        GDIM, DHH, EDIM, /*zA=*/EDIM, /*zB=*/DHH * EDIM, /*zC=*/DHH, /*zBias=*/DHH);

    // out = pooled @ Wc^T + cb   [256,256]
    gemm_s<true, true><<<dim3(OUTD / 32, GDIM / 64, 1), 128>>>(
        ppooled, EDIM, pWc, EDIM, out, OUTD, pcb,
        GDIM, OUTD, EDIM, 0, 0, 0, 0);
}

// round 12
// speedup vs baseline: 2.3177x; 2.3177x over previous
#include <cuda_runtime.h>
#include <math.h>
#include <stdint.h>

// Problem constants
#define EDIM 384
#define GDIM 256
#define HNUM 6
#define DHH  64
#define OUTD 256
#define HE   (HNUM*EDIM)   // 2304
#define CHUNK 16
#define UNIT 128
#define SLOTS 8            // MAX_N 1024 / UNIT
#define CFLOATS (CHUNK*EDIM)          // 6144 floats per buffer
#define SMEM_X (2*CFLOATS*4)          // 49152 B double buffer

// ---------------- device scratch ----------------
__device__ __align__(16) float g_wk[HNUM*EDIM];
__device__ __align__(16) float g_Wc[OUTD*EDIM];      // Wp @ Wo
__device__ __align__(16) float g_cb[OUTD];           // Wp.bo + bp
__device__            int   g_off[GDIM + 1];
__device__ __align__(16) float g_accx[GDIM*HE];      // merged attn-weighted x sums
__device__ __align__(16) float g_pooled[GDIM*EDIM];  // pooled incl. bv
// per-unit softmax partials; pacc layout [u][e][8] (heads padded to 8)
__device__ __align__(16) float g_pacc[(size_t)GDIM*SLOTS*EDIM*8];
__device__ __align__(16) float g_pm[GDIM*SLOTS*HNUM];
__device__ __align__(16) float g_psum[GDIM*SLOTS*HNUM];

// ---------------- helpers ----------------
__device__ __forceinline__ float warp_sum(float v) {
#pragma unroll
    for (int s = 16; s > 0; s >>= 1) v += __shfl_xor_sync(0xffffffffu, v, s);
    return v;
}
__device__ __forceinline__ float warp_max(float v) {
#pragma unroll
    for (int s = 16; s > 0; s >>= 1) v = fmaxf(v, __shfl_xor_sync(0xffffffffu, v, s));
    return v;
}
__device__ __forceinline__ void cp_async16(uint32_t saddr, const void* gaddr) {
    asm volatile("cp.async.cg.shared.global [%0], [%1], 16;" :: "r"(saddr), "l"(gaddr));
}
__device__ __forceinline__ void cp_commit() {
    asm volatile("cp.async.commit_group;");
}
__device__ __forceinline__ void cp_wait0() {
    asm volatile("cp.async.wait_group 0;");
}

// ---------------- prep: wkq (blocks 0..5) + scan (6) + cb (7..28) ----------
__global__ void __launch_bounds__(EDIM)
prep_kernel(const float* __restrict__ Wq, const float* __restrict__ query,
            const float* __restrict__ bq, const float* __restrict__ Wk,
            const int* __restrict__ sizes, const float* __restrict__ Wp,
            const float* __restrict__ bo, const float* __restrict__ bp) {
    int b = blockIdx.x;
    int tid = threadIdx.x;
    int warp = tid >> 5;
    int lane = tid & 31;
    if (b < HNUM) {
        int h = b;
        __shared__ float qs[DHH];
        for (int d = warp; d < DHH; d += 12) {
            int row = h * DHH + d;
            float s = 0.f;
            for (int j = lane; j < EDIM; j += 32) s += Wq[(size_t)row * EDIM + j] * query[j];
            s = warp_sum(s);
            if (lane == 0) qs[d] = (s + bq[row]) * 0.125f;
        }
        __syncthreads();
        float s = 0.f;
#pragma unroll 8
        for (int d = 0; d < DHH; d++)
            s += qs[d] * Wk[(size_t)(h * DHH + d) * EDIM + tid];
        g_wk[h * EDIM + tid] = s;
    } else if (b == HNUM) {
        __shared__ int s[GDIM];
        if (tid < GDIM) s[tid] = sizes[tid];
        __syncthreads();
        for (int d = 1; d < GDIM; d <<= 1) {
            int add = (tid < GDIM && tid >= d) ? s[tid - d] : 0;
            __syncthreads();
            if (tid < GDIM) s[tid] += add;
            __syncthreads();
        }
        if (tid < GDIM) {
            g_off[tid] = s[tid] - sizes[tid];
            if (tid == GDIM - 1) g_off[GDIM] = s[tid];
        }
    } else {
        int gw = (b - HNUM - 1) * 12 + warp;
        if (gw < OUTD) {
            float s = 0.f;
            for (int j = lane; j < EDIM; j += 32) s += Wp[(size_t)gw * EDIM + j] * bo[j];
            s = warp_sum(s);
            if (lane == 0) g_cb[gw] = s + bp[gw];
        }
    }
}

// ---------------- 64x32-tiled fp32 GEMM, 4x4 microtile, 128 threads ------
template <bool TB, bool BIAS>
__global__ void __launch_bounds__(128)
gemm_s(const float* __restrict__ A, int lda,
       const float* __restrict__ B, int ldb,
       float* __restrict__ C, int ldc,
       const float* __restrict__ bias,
       int M, int N, int K,
       int zA, int zB, int zC, int zBias) {
    A += (size_t)blockIdx.z * zA;
    B += (size_t)blockIdx.z * zB;
    C += (size_t)blockIdx.z * zC;
    if (BIAS) bias += (size_t)blockIdx.z * zBias;

    __shared__ float As[32][68];
    __shared__ float Bs[32][36];
    int tid = threadIdx.x;
    int bm = blockIdx.y * 64, bn = blockIdx.x * 32;
    int tx = tid & 7, ty = tid >> 3;

    float acc[4][4];
#pragma unroll
    for (int i = 0; i < 4; i++)
#pragma unroll
        for (int j = 0; j < 4; j++) acc[i][j] = 0.f;

    for (int k0 = 0; k0 < K; k0 += 32) {
        {
            int kk = tid & 31, mb = tid >> 5;
#pragma unroll
            for (int i = 0; i < 16; i++) {
                int mm = mb + i * 4;
                As[kk][mm] = A[(size_t)(bm + mm) * lda + k0 + kk];
            }
        }
        if (TB) {
            int kk = tid & 31, nb = tid >> 5;
#pragma unroll
            for (int i = 0; i < 8; i++) {
                int nn = nb + i * 4;
                Bs[kk][nn] = B[(size_t)(bn + nn) * ldb + k0 + kk];
            }
        } else {
            int nn = tid & 31, kb = tid >> 5;
#pragma unroll
            for (int i = 0; i < 8; i++) {
                int k2 = kb + i * 4;
                Bs[k2][nn] = B[(size_t)(k0 + k2) * ldb + bn + nn];
            }
        }
        __syncthreads();
#pragma unroll
        for (int kk = 0; kk < 32; kk++) {
            float4 a = *(const float4*)&As[kk][ty * 4];
            float4 bb = *(const float4*)&Bs[kk][tx * 4];
            acc[0][0] = fmaf(a.x, bb.x, acc[0][0]); acc[0][1] = fmaf(a.x, bb.y, acc[0][1]);
            acc[0][2] = fmaf(a.x, bb.z, acc[0][2]); acc[0][3] = fmaf(a.x, bb.w, acc[0][3]);
            acc[1][0] = fmaf(a.y, bb.x, acc[1][0]); acc[1][1] = fmaf(a.y, bb.y, acc[1][1]);
            acc[1][2] = fmaf(a.y, bb.z, acc[1][2]); acc[1][3] = fmaf(a.y, bb.w, acc[1][3]);
            acc[2][0] = fmaf(a.z, bb.x, acc[2][0]); acc[2][1] = fmaf(a.z, bb.y, acc[2][1]);
            acc[2][2] = fmaf(a.z, bb.z, acc[2][2]); acc[2][3] = fmaf(a.z, bb.w, acc[2][3]);
            acc[3][0] = fmaf(a.w, bb.x, acc[3][0]); acc[3][1] = fmaf(a.w, bb.y, acc[3][1]);
            acc[3][2] = fmaf(a.w, bb.z, acc[3][2]); acc[3][3] = fmaf(a.w, bb.w, acc[3][3]);
        }
        __syncthreads();
    }
    float4 bv4 = make_float4(0.f, 0.f, 0.f, 0.f);
    if (BIAS) bv4 = *(const float4*)&bias[bn + tx * 4];
#pragma unroll
    for (int i = 0; i < 4; i++) {
        int gm = bm + ty * 4 + i;
        float4 o = make_float4(acc[i][0] + bv4.x, acc[i][1] + bv4.y,
                               acc[i][2] + bv4.z, acc[i][3] + bv4.w);
        *(float4*)&C[(size_t)gm * ldc + bn + tx * 4] = o;
    }
}

// ---------------- attention unit kernel: cp.async double-buffered -----------
// block = (group, slot). 256 threads, chunks of 16 nodes, 2x24KB smem buffers.
// Heads split across warp halves: warps 0-3 -> heads 0-2, warps 4-7 -> heads 3-5
// (halves per-lane weight registers, enabling 3 blocks/SM).
extern __shared__ float x_s[];   // [2][CHUNK*EDIM]

__global__ void __launch_bounds__(256, 3)
attn_unit_kernel(const float* __restrict__ x, const int* __restrict__ sizes) {
    __shared__ float s_sc[CHUNK][8];
    __shared__ float s_run_m[HNUM], s_run_sum[HNUM], s_scale[HNUM];

    int u = blockIdx.x;
    int g = u >> 3;
    int slot = u & (SLOTS - 1);
    int size = sizes[g];
    int ustart = slot * UNIT;
    if (ustart >= size) return;
    int ucnt = min(UNIT, size - ustart);
    int off = g_off[g] + ustart;
    int nchunks = (ucnt + CHUNK - 1) / CHUNK;

    int tid = threadIdx.x;
    int warp = tid >> 5;
    int lane = tid & 31;
    int hgrp = warp >> 2;            // 0 or 1: heads hgrp*3 .. hgrp*3+2

    if (tid < HNUM) { s_run_m[tid] = -1e30f; s_run_sum[tid] = 0.f; }

    uint32_t smem_base = (uint32_t)__cvta_generic_to_shared(x_s);

    // per-lane score weights for this warp's 3 heads (36 regs)
    float4 w[3][3];
#pragma unroll
    for (int j3 = 0; j3 < 3; j3++)
#pragma unroll
        for (int j = 0; j < 3; j++)
            w[j3][j] = *(const float4*)(&g_wk[(hgrp * 3 + j3) * EDIM + j * 128 + lane * 4]);

    const bool two = (tid < 128);
    const int e2 = tid + 256;
    float acc1[HNUM], acc2[HNUM];
#pragma unroll
    for (int h = 0; h < HNUM; h++) { acc1[h] = 0.f; acc2[h] = 0.f; }

    // preload chunk 0 into buffer 0
    {
        int cnt0 = min(CHUNK, ucnt);
        const float4* gx = (const float4*)(x + (size_t)off * EDIM);
        int nf4 = cnt0 * (EDIM / 4);
        for (int i = tid; i < nf4; i += 256)
            cp_async16(smem_base + i * 16, gx + i);
    }
    cp_commit();

    for (int c = 0; c < nchunks; c++) {
        int c0 = c * CHUNK;
        int cnt = min(CHUNK, ucnt - c0);
        float* buf = x_s + (c & 1) * CFLOATS;

        cp_wait0();
        __syncthreads();

        // prefetch next chunk into the other buffer
        if (c + 1 < nchunks) {
            int n0 = (c + 1) * CHUNK;
            int cnt2 = min(CHUNK, ucnt - n0);
            const float4* gx = (const float4*)(x + (size_t)(off + n0) * EDIM);
            int nf4 = cnt2 * (EDIM / 4);
            uint32_t sb = smem_base + ((c + 1) & 1) * (CFLOATS * 4);
            for (int i = tid; i < nf4; i += 256)
                cp_async16(sb + i * 16, gx + i);
        }
        cp_commit();

        // phase 1: raw scores; warp (hgrp, warp&3) covers nodes (warp&3)+4k, 3 heads
        for (int nn = (warp & 3); nn < cnt; nn += 4) {
            const float4* rowv = (const float4*)(buf + nn * EDIM);
            float4 x0 = rowv[lane];
            float4 x1 = rowv[lane + 32];
            float4 x2 = rowv[lane + 64];
            float p[3];
#pragma unroll
            for (int j3 = 0; j3 < 3; j3++) {
                float s;
                s = w[j3][0].x * x0.x;           s = fmaf(w[j3][0].y, x0.y, s);
                s = fmaf(w[j3][0].z, x0.z, s);   s = fmaf(w[j3][0].w, x0.w, s);
                s = fmaf(w[j3][1].x, x1.x, s);   s = fmaf(w[j3][1].y, x1.y, s);
                s = fmaf(w[j3][1].z, x1.z, s);   s = fmaf(w[j3][1].w, x1.w, s);
                s = fmaf(w[j3][2].x, x2.x, s);   s = fmaf(w[j3][2].y, x2.y, s);
                s = fmaf(w[j3][2].z, x2.z, s);   s = fmaf(w[j3][2].w, x2.w, s);
                p[j3] = s;
            }
#pragma unroll
            for (int sft = 16; sft > 0; sft >>= 1)
#pragma unroll
                for (int j3 = 0; j3 < 3; j3++)
                    p[j3] += __shfl_xor_sync(0xffffffffu, p[j3], sft);
            if (lane == 0) {
#pragma unroll
                for (int j3 = 0; j3 < 3; j3++) s_sc[nn][hgrp * 3 + j3] = p[j3];
            }
        }
        __syncthreads();

        // phase 2: online softmax update (warp h owns head h, h<6)
        if (warp < HNUM) {
            int h = warp;
            float m = (lane < cnt) ? s_sc[lane][h] : -1e30f;
            m = warp_max(m);
            float newm = fmaxf(s_run_m[h], m);
            float e = (lane < cnt) ? __expf(s_sc[lane][h] - newm) : 0.f;
            if (lane < cnt) s_sc[lane][h] = e;
            float sum = warp_sum(e);
            if (lane == 0) {
                float sc = __expf(s_run_m[h] - newm);
                s_scale[h] = sc;
                s_run_sum[h] = s_run_sum[h] * sc + sum;
                s_run_m[h] = newm;
            }
        }
        __syncthreads();

        // phase 3: rescale + accumulate (1.5 cols/thread)
#pragma unroll
        for (int h = 0; h < HNUM; h++) {
            float sc = s_scale[h];
            acc1[h] *= sc;
            acc2[h] *= sc;
        }
        for (int nn = 0; nn < cnt; nn++) {
            float xv1 = buf[nn * EDIM + tid];
            float xv2 = two ? buf[nn * EDIM + e2] : 0.f;
            float4 a4 = *(const float4*)&s_sc[nn][0];
            float2 a2 = *(const float2*)&s_sc[nn][4];
            acc1[0] = fmaf(a4.x, xv1, acc1[0]);  acc2[0] = fmaf(a4.x, xv2, acc2[0]);
            acc1[1] = fmaf(a4.y, xv1, acc1[1]);  acc2[1] = fmaf(a4.y, xv2, acc2[1]);
            acc1[2] = fmaf(a4.z, xv1, acc1[2]);  acc2[2] = fmaf(a4.z, xv2, acc2[2]);
            acc1[3] = fmaf(a4.w, xv1, acc1[3]);  acc2[3] = fmaf(a4.w, xv2, acc2[3]);
            acc1[4] = fmaf(a2.x, xv1, acc1[4]);  acc2[4] = fmaf(a2.x, xv2, acc2[4]);
            acc1[5] = fmaf(a2.y, xv1, acc1[5]);  acc2[5] = fmaf(a2.y, xv2, acc2[5]);
        }
        __syncthreads();
    }

    // write unnormalized partials: pacc[u][e][8], float4 pairs
    {
        float4* pp = (float4*)&g_pacc[((size_t)u * EDIM + tid) * 8];
        pp[0] = make_float4(acc1[0], acc1[1], acc1[2], acc1[3]);
        pp[1] = make_float4(acc1[4], acc1[5], 0.f, 0.f);
        if (two) {
            float4* pq = (float4*)&g_pacc[((size_t)u * EDIM + e2) * 8];
            pq[0] = make_float4(acc2[0], acc2[1], acc2[2], acc2[3]);
            pq[1] = make_float4(acc2[4], acc2[5], 0.f, 0.f);
        }
    }
    if (tid < HNUM) {
        g_pm[u * HNUM + tid] = s_run_m[tid];
        g_psum[u * HNUM + tid] = s_run_sum[tid];
    }
}

// ---------------- merge partials -> normalized accx ----------------
// grid (GDIM, 3): block handles 128 columns of one group.
__global__ void __launch_bounds__(128)
merge_kernel(const int* __restrict__ sizes) {
    __shared__ float s_w[SLOTS][HNUM];
    int g = blockIdx.x;
    int e = blockIdx.y * 128 + threadIdx.x;
    int size = sizes[g];
    int nslots = (size + UNIT - 1) / UNIT;
    int tid = threadIdx.x;

    if (tid < HNUM) {
        int h = tid;
        float M = -1e30f;
        for (int s = 0; s < nslots; s++)
            M = fmaxf(M, g_pm[(g * SLOTS + s) * HNUM + h]);
        float denom = 0.f;
        for (int s = 0; s < nslots; s++) {
            float sc = __expf(g_pm[(g * SLOTS + s) * HNUM + h] - M);
            s_w[s][h] = sc;
            denom += sc * g_psum[(g * SLOTS + s) * HNUM + h];
        }
        float inv = 1.f / denom;
        for (int s = 0; s < nslots; s++) s_w[s][h] *= inv;
    }
    __syncthreads();

    float acc[HNUM];
#pragma unroll
    for (int h = 0; h < HNUM; h++) acc[h] = 0.f;
    for (int s = 0; s < nslots; s++) {
        const float4* pp = (const float4*)&g_pacc[((size_t)(g * SLOTS + s) * EDIM + e) * 8];
        float4 p0 = pp[0];
        float4 p1 = pp[1];
        acc[0] = fmaf(s_w[s][0], p0.x, acc[0]);
        acc[1] = fmaf(s_w[s][1], p0.y, acc[1]);
        acc[2] = fmaf(s_w[s][2], p0.z, acc[2]);
        acc[3] = fmaf(s_w[s][3], p0.w, acc[3]);
        acc[4] = fmaf(s_w[s][4], p1.x, acc[4]);
        acc[5] = fmaf(s_w[s][5], p1.y, acc[5]);
    }
#pragma unroll
    for (int h = 0; h < HNUM; h++)
        g_accx[(size_t)g * HE + h * EDIM + e] = acc[h];
}

// ---------------- launch ----------------
extern "C" void kernel_launch(void* const* d_in, const int* in_sizes, int n_in,
                              void* d_out, int out_size) {
    const float* node_feat = (const float*)d_in[0];
    const int*   sizes     = (const int*)d_in[1];
    const float* query     = (const float*)d_in[2];
    const float* Wq        = (const float*)d_in[3];
    const float* bq        = (const float*)d_in[4];
    const float* Wk        = (const float*)d_in[5];
    /* bk = d_in[6] cancels in softmax */
    const float* Wv        = (const float*)d_in[7];
    const float* bv        = (const float*)d_in[8];
    const float* Wo        = (const float*)d_in[9];
    const float* bo        = (const float*)d_in[10];
    const float* Wp        = (const float*)d_in[11];
    const float* bp        = (const float*)d_in[12];
    float* out = (float*)d_out;

    float *pWc, *pcb, *paccx, *ppooled;
    cudaGetSymbolAddress((void**)&pWc, g_Wc);
    cudaGetSymbolAddress((void**)&pcb, g_cb);
    cudaGetSymbolAddress((void**)&paccx, g_accx);
    cudaGetSymbolAddress((void**)&ppooled, g_pooled);

    cudaFuncSetAttribute(attn_unit_kernel,
                         cudaFuncAttributeMaxDynamicSharedMemorySize, SMEM_X);

    // prep: wkq + scan + cb in one launch
    prep_kernel<<<HNUM + 1 + 22, EDIM>>>(Wq, query, bq, Wk, sizes, Wp, bo, bp);

    // Wc = Wp @ Wo   [256,384]
    gemm_s<false, false><<<dim3(EDIM / 32, OUTD / 64, 1), 128>>>(
        Wp, EDIM, Wo, EDIM, pWc, EDIM, nullptr, OUTD, EDIM, EDIM, 0, 0, 0, 0);

    // attention partials + merge
    attn_unit_kernel<<<GDIM * SLOTS, 256, SMEM_X>>>(node_feat, sizes);
    merge_kernel<<<dim3(GDIM, 3), 128>>>(sizes);

    // pooled[g, h*64+d] = bv + Wv_h . accx_h   (batched over h)
    gemm_s<true, true><<<dim3(DHH / 32, GDIM / 64, HNUM), 128>>>(
        paccx, HE, Wv, EDIM, ppooled, EDIM, bv,
        GDIM, DHH, EDIM, /*zA=*/EDIM, /*zB=*/DHH * EDIM, /*zC=*/DHH, /*zBias=*/DHH);

    // out = pooled @ Wc^T + cb   [256,256]
    gemm_s<true, true><<<dim3(OUTD / 32, GDIM / 64, 1), 128>>>(
        ppooled, EDIM, pWc, EDIM, out, OUTD, pcb,
        GDIM, OUTD, EDIM, 0, 0, 0, 0);
}